// round 1
// baseline (speedup 1.0000x reference)
#include <cuda_runtime.h>
#include <cuda_bf16.h>

// HighDimAELoss: associative-embedding push/pull loss.
// tags:   [B=16, D=17, R=512, R=512] float32
// joints: [B=16, M=30, J=17, 2] int32  (flat heatmap idx, visibility)
// out:    [2*B] float32  -> out[0:16]=push, out[16:32]=pull

#define B_IMG   16
#define M_PPL   30
#define N_JNT   17
#define AE_D    17
#define RESO    512
#define NTHREADS 256

__global__ __launch_bounds__(NTHREADS)
void ae_loss_kernel(const float* __restrict__ tags,
                    const int*   __restrict__ joints,
                    float*       __restrict__ out) {
    const int b   = blockIdx.x;
    const int tid = threadIdx.x;

    // shared staging
    __shared__ float tS[M_PPL * N_JNT * AE_D];   // gathered tag vectors [m][j][d]
    __shared__ float validS[M_PPL * N_JNT];
    __shared__ float sqS[M_PPL * N_JNT];         // per-joint pairwise-sq sum
    __shared__ float cntS[M_PPL];
    __shared__ float meanS[M_PPL * AE_D];
    __shared__ float pvS[M_PPL];                 // person_valid
    __shared__ int   xS[M_PPL * N_JNT];
    __shared__ int   yS[M_PPL * N_JNT];
    __shared__ float red[NTHREADS];
    __shared__ float s_pull, s_ntags;

    const float* tagb = tags + (size_t)b * AE_D * RESO * RESO;
    const int*   jb   = joints + (size_t)b * M_PPL * N_JNT * 2;

    // 1) decode joint coords + validity
    for (int i = tid; i < M_PPL * N_JNT; i += NTHREADS) {
        int idx = jb[2 * i];
        int vis = jb[2 * i + 1];
        int off = idx % (RESO * RESO);
        if (off < 0) off += RESO * RESO;   // python-style mod safety
        int x = off % RESO;                // 2nd axis of pred_tag
        int y = off / RESO;                // 3rd axis
        xS[i] = x;
        yS[i] = y;
        validS[i] = (vis > 0) ? 1.0f : 0.0f;
    }
    __syncthreads();

    // 2) gather tag vectors: t[m][j][d] = tags[b, d, x, y]
    //    8670 independent scattered loads per image -> high MLP, latency-hidden
    for (int e = tid; e < M_PPL * N_JNT * AE_D; e += NTHREADS) {
        int d  = e % AE_D;
        int mj = e / AE_D;
        tS[mj * AE_D + d] =
            __ldg(&tagb[(size_t)d * (RESO * RESO) + (size_t)xS[mj] * RESO + yS[mj]]);
    }
    __syncthreads();

    // 3) per-joint pairwise-squared sum over D dims:
    //    sum_{d,e}(t_d - t_e)^2 = 2*D*sum(t^2) - 2*(sum t)^2
    for (int i = tid; i < M_PPL * N_JNT; i += NTHREADS) {
        float s1 = 0.f, s2 = 0.f;
        #pragma unroll
        for (int d = 0; d < AE_D; d++) {
            float v = tS[i * AE_D + d];
            s1 += v;
            s2 += v * v;
        }
        sqS[i] = 2.0f * (float)AE_D * s2 - 2.0f * s1 * s1;
    }

    // 4) per-person count + mean tag (task per (m,d))
    for (int i = tid; i < M_PPL * AE_D; i += NTHREADS) {
        int m = i / AE_D;
        int d = i % AE_D;
        float acc = 0.f, c = 0.f;
        #pragma unroll
        for (int j = 0; j < N_JNT; j++) {
            float v = validS[m * N_JNT + j];
            acc += tS[(m * N_JNT + j) * AE_D + d] * v;
            c   += v;
        }
        float safe = fmaxf(c, 1.0f);
        meanS[i] = acc / safe;
        if (d == 0) {
            cntS[m] = c;
            pvS[m]  = (c > 0.f) ? 1.0f : 0.0f;
        }
    }
    __syncthreads();

    // 5) pull + n_tags: tiny (M=30), serial on thread 0 -> deterministic
    if (tid == 0) {
        float pull = 0.f, ntags = 0.f;
        for (int m = 0; m < M_PPL; m++) {
            float c = cntS[m];
            float safe = fmaxf(c, 1.0f);
            float pp = 0.f;
            for (int j = 0; j < N_JNT; j++)
                pp += sqS[m * N_JNT + j] * validS[m * N_JNT + j];
            pp /= ((float)(AE_D * AE_D) * safe);
            pull  += pp * pvS[m];
            ntags += pvS[m];
        }
        s_pull  = pull / fmaxf(ntags, 1.0f);
        s_ntags = ntags;
    }
    __syncthreads();

    // 6) push: pairwise exp(-diff^2) between mean tags (diagonal included)
    float local = 0.f;
    for (int p = tid; p < M_PPL * M_PPL; p += NTHREADS) {
        int m = p / M_PPL;
        int n = p % M_PPL;
        float w = pvS[m] * pvS[n];
        if (w > 0.f) {
            float s = 0.f;
            #pragma unroll
            for (int d = 0; d < AE_D; d++) {
                float dd = meanS[m * AE_D + d] - meanS[n * AE_D + d];
                s += __expf(-dd * dd);
            }
            local += s * (1.0f / (float)AE_D);
        }
    }
    red[tid] = local;
    __syncthreads();
    // deterministic tree reduction
    for (int stride = NTHREADS / 2; stride > 0; stride >>= 1) {
        if (tid < stride) red[tid] += red[tid + stride];
        __syncthreads();
    }

    if (tid == 0) {
        float nt = s_ntags;
        float denom = fmaxf(nt, 1.0f);
        float push = (nt >= 2.0f) ? red[0] / (denom * denom) : 0.0f;
        out[b]         = push;   // first returned value
        out[B_IMG + b] = s_pull; // second returned value
    }
}

extern "C" void kernel_launch(void* const* d_in, const int* in_sizes, int n_in,
                              void* d_out, int out_size) {
    const float* tags   = (const float*)d_in[0];
    const int*   joints = (const int*)d_in[1];
    float*       out    = (float*)d_out;
    ae_loss_kernel<<<B_IMG, NTHREADS>>>(tags, joints, out);
}

// round 3
// speedup vs baseline: 1.7672x; 1.7672x over previous
#include <cuda_runtime.h>
#include <cuda_bf16.h>

// HighDimAELoss: associative-embedding push/pull loss.
// tags:   [B=16, D=17, R=512, R=512] float32
// joints: [B=16, M=30, J=17, 2] int32  (flat heatmap idx, visibility)
// out:    [2*B] float32  -> out[0:16]=push, out[16:32]=pull
//
// Two-phase: per-person kernel (480 CTAs, spreads the scattered gather over
// the whole chip) -> per-image finalize kernel (16 CTAs).

#define B_IMG   16
#define M_PPL   30
#define N_JNT   17
#define AE_D    17
#define AE_DP   18          // padded row to avoid smem bank conflicts
#define RESO    512

// scratch (device globals - no allocation allowed)
__device__ float g_mean [B_IMG * M_PPL * AE_D];
__device__ float g_pv   [B_IMG * M_PPL];
__device__ float g_pullc[B_IMG * M_PPL];   // pull_p * person_valid

// ---------------------------------------------------------------------------
// Kernel 1: one CTA per (image, person)
// ---------------------------------------------------------------------------
#define K1_THREADS 128

__global__ __launch_bounds__(K1_THREADS)
void ae_person_kernel(const float* __restrict__ tags,
                      const int*   __restrict__ joints) {
    const int bm  = blockIdx.x;          // b * M_PPL + m
    const int b   = bm / M_PPL;
    const int tid = threadIdx.x;

    __shared__ float tS[N_JNT * AE_DP];  // gathered tag vectors [j][d], padded
    __shared__ float validS[N_JNT];
    __shared__ int   xS[N_JNT];
    __shared__ int   yS[N_JNT];
    __shared__ float sqS[N_JNT];         // per-joint pairwise-sq sum
    __shared__ float s_cnt;

    const float* tagb = tags + (size_t)b * AE_D * RESO * RESO;
    const int*   jb   = joints + (size_t)bm * N_JNT * 2;

    // decode joints
    if (tid < N_JNT) {
        int idx = jb[2 * tid];
        int vis = jb[2 * tid + 1];
        int off = idx % (RESO * RESO);
        if (off < 0) off += RESO * RESO;
        xS[tid] = off % RESO;
        yS[tid] = off / RESO;
        validS[tid] = (vis > 0) ? 1.0f : 0.0f;
    }
    __syncthreads();

    // gather 289 scattered values: t[j][d] = tags[b, d, x_j, y_j]
    for (int e = tid; e < N_JNT * AE_D; e += K1_THREADS) {
        int d = e % AE_D;
        int j = e / AE_D;
        tS[j * AE_DP + d] =
            __ldg(&tagb[(size_t)d * (RESO * RESO) + (size_t)xS[j] * RESO + yS[j]]);
    }
    __syncthreads();

    // per-joint pairwise-squared sum over D:
    // sum_{d,e}(t_d - t_e)^2 = 2*D*sum(t^2) - 2*(sum t)^2
    if (tid < N_JNT) {
        float s1 = 0.f, s2 = 0.f;
        #pragma unroll
        for (int d = 0; d < AE_D; d++) {
            float v = tS[tid * AE_DP + d];
            s1 += v; s2 += v * v;
        }
        sqS[tid] = 2.0f * (float)AE_D * s2 - 2.0f * s1 * s1;
        if (tid == 0) {
            float c = 0.f;
            #pragma unroll
            for (int j = 0; j < N_JNT; j++) c += validS[j];
            s_cnt = c;
        }
    }
    __syncthreads();

    const float cnt  = s_cnt;
    const float safe = fmaxf(cnt, 1.0f);
    const float pv   = (cnt > 0.f) ? 1.0f : 0.0f;

    // mean tag per dim
    if (tid < AE_D) {
        float acc = 0.f;
        #pragma unroll
        for (int j = 0; j < N_JNT; j++)
            acc += tS[j * AE_DP + tid] * validS[j];
        g_mean[bm * AE_D + tid] = acc / safe;
    }

    // pull contribution (deterministic serial over 17)
    if (tid == 0) {
        float pp = 0.f;
        #pragma unroll
        for (int j = 0; j < N_JNT; j++) pp += sqS[j] * validS[j];
        pp /= ((float)(AE_D * AE_D) * safe);
        g_pullc[bm] = pp * pv;
        g_pv[bm]    = pv;
    }
}

// ---------------------------------------------------------------------------
// Kernel 2: one CTA per image - push + finalize pull
// ---------------------------------------------------------------------------
#define K2_THREADS 256

__global__ __launch_bounds__(K2_THREADS)
void ae_image_kernel(float* __restrict__ out) {
    const int b   = blockIdx.x;
    const int tid = threadIdx.x;

    __shared__ float meanS[M_PPL * AE_D];
    __shared__ float pvS[M_PPL];
    __shared__ float red[K2_THREADS];
    __shared__ float s_pull, s_ntags;

    for (int i = tid; i < M_PPL * AE_D; i += K2_THREADS)
        meanS[i] = g_mean[b * M_PPL * AE_D + i];
    if (tid < M_PPL) pvS[tid] = g_pv[b * M_PPL + tid];
    if (tid == 0) {
        float pull = 0.f, ntags = 0.f;
        for (int m = 0; m < M_PPL; m++) {
            pull  += g_pullc[b * M_PPL + m];
            ntags += g_pv[b * M_PPL + m];
        }
        s_pull  = pull / fmaxf(ntags, 1.0f);
        s_ntags = ntags;
    }
    __syncthreads();

    // push: pairwise exp(-diff^2) between mean tags (diagonal included)
    float local = 0.f;
    for (int p = tid; p < M_PPL * M_PPL; p += K2_THREADS) {
        int m = p / M_PPL;
        int n = p % M_PPL;
        float w = pvS[m] * pvS[n];
        if (w > 0.f) {
            float s = 0.f;
            #pragma unroll
            for (int d = 0; d < AE_D; d++) {
                float dd = meanS[m * AE_D + d] - meanS[n * AE_D + d];
                s += __expf(-dd * dd);
            }
            local += s * (1.0f / (float)AE_D);
        }
    }
    red[tid] = local;
    __syncthreads();
    for (int stride = K2_THREADS / 2; stride > 0; stride >>= 1) {
        if (tid < stride) red[tid] += red[tid + stride];
        __syncthreads();
    }

    if (tid == 0) {
        float nt    = s_ntags;
        float denom = fmaxf(nt, 1.0f);
        out[b]         = (nt >= 2.0f) ? red[0] / (denom * denom) : 0.0f; // push
        out[B_IMG + b] = s_pull;                                         // pull
    }
}

extern "C" void kernel_launch(void* const* d_in, const int* in_sizes, int n_in,
                              void* d_out, int out_size) {
    const float* tags   = (const float*)d_in[0];
    const int*   joints = (const int*)d_in[1];
    float*       out    = (float*)d_out;
    ae_person_kernel<<<B_IMG * M_PPL, K1_THREADS>>>(tags, joints);
    ae_image_kernel<<<B_IMG, K2_THREADS>>>(out);
}